// round 9
// baseline (speedup 1.0000x reference)
#include <cuda_runtime.h>
#include <cuda_bf16.h>
#include <cstdint>

#define NB 4096
#define NT 200
#define ND 64
#define NH1 128
#define NH2 64
#define NTHREADS 512

// All operand tiles use natural row pitch (128B or 256B) with a per-row
// chunk-XOR swizzle: physical_16B_chunk = logical_chunk ^ (row & 7).
struct __align__(16) Smem {
    char Ahi[208 * 128];   // hist hi  [208 rows][64 bf16]
    char Alo[208 * 128];
    char B1hi[128 * 128];  // Weff^T   [128 n][64 k]
    char B1lo[128 * 128];
    char Hhi[208 * 256];   // layer-1 out [208 rows][128 bf16]
    char Hlo[208 * 256];
    char B2hi[64 * 256];   // W2^T     [64 n][128 k]
    char B2lo[64 * 256];
    float u[NH1];
    float b2s[NH2], w3s[NH2];
    float scores[208];
    float weights[NT];
    float partial[8][ND];
    float invsum;
};

__device__ __forceinline__ uint32_t smem_u32(const void* p) {
    uint32_t a;
    asm("{ .reg .u64 t; cvta.to.shared.u64 t, %1; cvt.u32.u64 %0, t; }" : "=r"(a) : "l"(p));
    return a;
}
__device__ __forceinline__ void ldsm4(uint32_t* r, uint32_t addr) {
    asm volatile("ldmatrix.sync.aligned.m8n8.x4.shared.b16 {%0,%1,%2,%3}, [%4];"
        : "=r"(r[0]), "=r"(r[1]), "=r"(r[2]), "=r"(r[3]) : "r"(addr));
}
__device__ __forceinline__ void mma16816(float* c, const uint32_t* a, const uint32_t* b) {
    asm volatile("mma.sync.aligned.m16n8k16.row.col.f32.bf16.bf16.f32 "
        "{%0,%1,%2,%3}, {%4,%5,%6,%7}, {%8,%9}, {%0,%1,%2,%3};"
        : "+f"(c[0]), "+f"(c[1]), "+f"(c[2]), "+f"(c[3])
        : "r"(a[0]), "r"(a[1]), "r"(a[2]), "r"(a[3]), "r"(b[0]), "r"(b[1]));
}
__device__ __forceinline__ void split_pair(float x0, float x1, uint32_t& hi, uint32_t& lo) {
    __nv_bfloat16 h0 = __float2bfloat16_rn(x0);
    __nv_bfloat16 h1 = __float2bfloat16_rn(x1);
    float r0 = x0 - __bfloat162float(h0);
    float r1 = x1 - __bfloat162float(h1);
    __nv_bfloat162 H; H.x = h0; H.y = h1;
    __nv_bfloat162 L = __floats2bfloat162_rn(r0, r1);
    hi = *reinterpret_cast<uint32_t*>(&H);
    lo = *reinterpret_cast<uint32_t*>(&L);
}
__device__ __forceinline__ void split_one(float x, uint16_t& hi, uint16_t& lo) {
    __nv_bfloat16 h = __float2bfloat16_rn(x);
    __nv_bfloat16 l = __float2bfloat16_rn(x - __bfloat162float(h));
    hi = *reinterpret_cast<uint16_t*>(&h);
    lo = *reinterpret_cast<uint16_t*>(&l);
}

__global__ void __launch_bounds__(NTHREADS, 1)
attention_unit_kernel(const float* __restrict__ cand_g,
                      const float* __restrict__ hist_g,
                      const int*   __restrict__ mask_g,
                      const float* __restrict__ W1,
                      const float* __restrict__ b1,
                      const float* __restrict__ W2,
                      const float* __restrict__ b2,
                      const float* __restrict__ W3,
                      const float* __restrict__ b3,
                      float* __restrict__ out)
{
    extern __shared__ __align__(16) char smem_raw[];
    Smem& s = *reinterpret_cast<Smem*>(smem_raw);

    const int b    = blockIdx.x;
    const int tid  = threadIdx.x;
    const int warp = tid >> 5;
    const int lane = tid & 31;

    // =================== Phase 0: stage + split everything ===================
    {
        const float4* hg = reinterpret_cast<const float4*>(hist_g + (size_t)b * NT * ND);
        for (int i = tid; i < NT * ND / 4; i += NTHREADS) {
            float4 v = hg[i];
            int t = i >> 4, q = i & 15;
            uint32_t h01, l01, h23, l23;
            split_pair(v.x, v.y, h01, l01);
            split_pair(v.z, v.w, h23, l23);
            uint32_t off = (uint32_t)(t * 128 + (((q >> 1) ^ (t & 7)) << 4) + (q & 1) * 8);
            *reinterpret_cast<uint2*>(s.Ahi + off) = make_uint2(h01, h23);
            *reinterpret_cast<uint2*>(s.Alo + off) = make_uint2(l01, l23);
        }
        for (int i = tid; i < 8 * 128 / 8; i += NTHREADS) {
            reinterpret_cast<uint2*>(s.Ahi + 200 * 128)[i] = make_uint2(0, 0);
            reinterpret_cast<uint2*>(s.Alo + 200 * 128)[i] = make_uint2(0, 0);
        }
    }
    {
        int h = tid & 127, dg = tid >> 7;
        #pragma unroll 4
        for (int dd = 0; dd < 16; dd++) {
            int d = dg * 16 + dd;
            float cd = __ldg(&cand_g[(size_t)b * ND + d]);
            float w = W1[(64 + d) * NH1 + h] - W1[(128 + d) * NH1 + h]
                    + cd * W1[(192 + d) * NH1 + h];
            uint16_t hi, lo; split_one(w, hi, lo);
            uint32_t off = (uint32_t)(h * 128 + (((d >> 3) ^ (h & 7)) << 4) + (d & 7) * 2);
            *reinterpret_cast<uint16_t*>(s.B1hi + off) = hi;
            *reinterpret_cast<uint16_t*>(s.B1lo + off) = lo;
        }
    }
    if (tid < NH1) {
        float acc = b1[tid];
        #pragma unroll 4
        for (int d = 0; d < ND; d++)
            acc += __ldg(&cand_g[(size_t)b * ND + d])
                 * (W1[d * NH1 + tid] + W1[(128 + d) * NH1 + tid]);
        s.u[tid] = acc;
    }
    {
        int j = tid & 63, kg = tid >> 6;
        #pragma unroll 4
        for (int kk = 0; kk < 16; kk++) {
            int k = kg * 16 + kk;
            uint16_t hi, lo; split_one(W2[k * NH2 + j], hi, lo);
            uint32_t off = (uint32_t)(j * 256 + (((k >> 3) ^ (j & 7)) << 4) + (k & 7) * 2);
            *reinterpret_cast<uint16_t*>(s.B2hi + off) = hi;
            *reinterpret_cast<uint16_t*>(s.B2lo + off) = lo;
        }
    }
    if (tid < NH2) { s.b2s[tid] = b2[tid]; s.w3s[tid] = W3[tid]; }
    if (tid < NT)  s.scores[tid] = b3[0];
    __syncthreads();

    const uint32_t pAhi = smem_u32(s.Ahi), pAlo = smem_u32(s.Alo);
    const uint32_t pB1h = smem_u32(s.B1hi), pB1l = smem_u32(s.B1lo);
    const uint32_t pHhi = smem_u32(s.Hhi), pHlo = smem_u32(s.Hlo);
    const uint32_t pB2h = smem_u32(s.B2hi), pB2l = smem_u32(s.B2lo);

    const int lrow = lane & 15, lkh = lane >> 4;
    const int bn   = ((lane >> 4) << 3) + (lane & 7);
    const int bk   = (lane >> 3) & 1;

    // ========== GEMM1: warp owns nt = warp&3; B1 fragments hoisted; loop mt ==========
    {
        const int nt  = warp & 3;
        const int mt0 = warp >> 2;

        uint32_t B1h[4][2][4], B1l[4][2][4];
        #pragma unroll
        for (int kk = 0; kk < 4; kk++)
            #pragma unroll
            for (int p = 0; p < 2; p++) {
                int brow = nt * 32 + p * 16 + bn;
                uint32_t boff = (uint32_t)(brow * 128 + (((kk * 2 + bk) ^ (brow & 7)) << 4));
                ldsm4(B1h[kk][p], pB1h + boff);
                ldsm4(B1l[kk][p], pB1l + boff);
            }

        for (int mt = mt0; mt < 13; mt += 4) {
            float acc[16];
            #pragma unroll
            for (int i = 0; i < 16; i++) acc[i] = 0.f;
            int arow = mt * 16 + lrow;

            #pragma unroll
            for (int kk = 0; kk < 4; kk++) {
                uint32_t ra[4], rl[4];
                uint32_t aoff = (uint32_t)(arow * 128 + (((kk * 2 + lkh) ^ (arow & 7)) << 4));
                ldsm4(ra, pAhi + aoff);
                ldsm4(rl, pAlo + aoff);
                #pragma unroll
                for (int f = 0; f < 4; f++) {
                    const uint32_t* bh = &B1h[kk][f >> 1][(f & 1) * 2];
                    const uint32_t* bl = &B1l[kk][f >> 1][(f & 1) * 2];
                    mma16816(acc + f * 4, ra, bh);
                    mma16816(acc + f * 4, ra, bl);
                    mma16816(acc + f * 4, rl, bh);
                }
            }
            // epilogue: +u, relu, split, store H
            int rlo = mt * 16 + (lane >> 2);
            #pragma unroll
            for (int f = 0; f < 4; f++) {
                int col = nt * 32 + f * 8 + (lane & 3) * 2;
                float u0 = s.u[col], u1 = s.u[col + 1];
                uint32_t h0, l0, h1, l1;
                split_pair(fmaxf(acc[f * 4 + 0] + u0, 0.f), fmaxf(acc[f * 4 + 1] + u1, 0.f), h0, l0);
                split_pair(fmaxf(acc[f * 4 + 2] + u0, 0.f), fmaxf(acc[f * 4 + 3] + u1, 0.f), h1, l1);
                int ch = col >> 3, wb = (col & 7) * 2;
                uint32_t o0 = (uint32_t)(rlo * 256 + ((ch ^ (rlo & 7)) << 4) + wb);
                uint32_t o1 = o0 + 8 * 256;
                *reinterpret_cast<uint32_t*>(s.Hhi + o0) = h0;
                *reinterpret_cast<uint32_t*>(s.Hhi + o1) = h1;
                *reinterpret_cast<uint32_t*>(s.Hlo + o0) = l0;
                *reinterpret_cast<uint32_t*>(s.Hlo + o1) = l1;
            }
        }
    }
    __syncthreads();

    // ========== GEMM2: warp owns nt = warp&1, mt0 = warp>>1 ({mt0, mt0+8}) ==========
    {
        const int nt  = warp & 1;
        const int mt0 = warp >> 1;

        if (mt0 <= 4) {
            // two m-tiles share hoisted B2 fragments
            float acc[2][16];
            #pragma unroll
            for (int i = 0; i < 2; i++)
                #pragma unroll
                for (int j = 0; j < 16; j++) acc[i][j] = 0.f;

            #pragma unroll
            for (int kb = 0; kb < 4; kb++) {
                uint32_t B2h[2][2][4], B2l[2][2][4];
                #pragma unroll
                for (int j = 0; j < 2; j++)
                    #pragma unroll
                    for (int p = 0; p < 2; p++) {
                        int kk = kb * 2 + j;
                        int brow = nt * 32 + p * 16 + bn;
                        uint32_t boff = (uint32_t)(brow * 256 + (((kk * 2 + bk) ^ (brow & 7)) << 4));
                        ldsm4(B2h[j][p], pB2h + boff);
                        ldsm4(B2l[j][p], pB2l + boff);
                    }
                #pragma unroll
                for (int i = 0; i < 2; i++) {
                    int arow = (mt0 + i * 8) * 16 + lrow;
                    #pragma unroll
                    for (int j = 0; j < 2; j++) {
                        int kk = kb * 2 + j;
                        uint32_t ra[4], rl[4];
                        uint32_t aoff = (uint32_t)(arow * 256 + (((kk * 2 + lkh) ^ (arow & 7)) << 4));
                        ldsm4(ra, pHhi + aoff);
                        ldsm4(rl, pHlo + aoff);
                        #pragma unroll
                        for (int f = 0; f < 4; f++) {
                            const uint32_t* bh = &B2h[j][f >> 1][(f & 1) * 2];
                            const uint32_t* bl = &B2l[j][f >> 1][(f & 1) * 2];
                            mma16816(acc[i] + f * 4, ra, bh);
                            mma16816(acc[i] + f * 4, ra, bl);
                            mma16816(acc[i] + f * 4, rl, bh);
                        }
                    }
                }
            }
            #pragma unroll
            for (int i = 0; i < 2; i++) {
                int mt = mt0 + i * 8;
                float vlo = 0.f, vhi = 0.f;
                #pragma unroll
                for (int f = 0; f < 4; f++) {
                    int col = nt * 32 + f * 8 + (lane & 3) * 2;
                    float b20 = s.b2s[col], b21 = s.b2s[col + 1];
                    float w30 = s.w3s[col], w31 = s.w3s[col + 1];
                    vlo += fmaxf(acc[i][f * 4 + 0] + b20, 0.f) * w30 + fmaxf(acc[i][f * 4 + 1] + b21, 0.f) * w31;
                    vhi += fmaxf(acc[i][f * 4 + 2] + b20, 0.f) * w30 + fmaxf(acc[i][f * 4 + 3] + b21, 0.f) * w31;
                }
                vlo += __shfl_xor_sync(0xFFFFFFFFu, vlo, 1);
                vlo += __shfl_xor_sync(0xFFFFFFFFu, vlo, 2);
                vhi += __shfl_xor_sync(0xFFFFFFFFu, vhi, 1);
                vhi += __shfl_xor_sync(0xFFFFFFFFu, vhi, 2);
                if ((lane & 3) == 0) {
                    int rlo = mt * 16 + (lane >> 2);
                    atomicAdd(&s.scores[rlo], vlo);
                    int rhi = rlo + 8;
                    if (rhi < NT) atomicAdd(&s.scores[rhi], vhi);
                }
            }
        } else {
            // single m-tile (mt0 in 5..7)
            float acc[16];
            #pragma unroll
            for (int j = 0; j < 16; j++) acc[j] = 0.f;
            int arow = mt0 * 16 + lrow;

            #pragma unroll
            for (int kk = 0; kk < 8; kk++) {
                uint32_t ra[4], rl[4], rbh[2][4], rbl[2][4];
                uint32_t aoff = (uint32_t)(arow * 256 + (((kk * 2 + lkh) ^ (arow & 7)) << 4));
                ldsm4(ra, pHhi + aoff);
                ldsm4(rl, pHlo + aoff);
                #pragma unroll
                for (int p = 0; p < 2; p++) {
                    int brow = nt * 32 + p * 16 + bn;
                    uint32_t boff = (uint32_t)(brow * 256 + (((kk * 2 + bk) ^ (brow & 7)) << 4));
                    ldsm4(rbh[p], pB2h + boff);
                    ldsm4(rbl[p], pB2l + boff);
                }
                #pragma unroll
                for (int f = 0; f < 4; f++) {
                    const uint32_t* bh = &rbh[f >> 1][(f & 1) * 2];
                    const uint32_t* bl = &rbl[f >> 1][(f & 1) * 2];
                    mma16816(acc + f * 4, ra, bh);
                    mma16816(acc + f * 4, ra, bl);
                    mma16816(acc + f * 4, rl, bh);
                }
            }
            float vlo = 0.f, vhi = 0.f;
            #pragma unroll
            for (int f = 0; f < 4; f++) {
                int col = nt * 32 + f * 8 + (lane & 3) * 2;
                float b20 = s.b2s[col], b21 = s.b2s[col + 1];
                float w30 = s.w3s[col], w31 = s.w3s[col + 1];
                vlo += fmaxf(acc[f * 4 + 0] + b20, 0.f) * w30 + fmaxf(acc[f * 4 + 1] + b21, 0.f) * w31;
                vhi += fmaxf(acc[f * 4 + 2] + b20, 0.f) * w30 + fmaxf(acc[f * 4 + 3] + b21, 0.f) * w31;
            }
            vlo += __shfl_xor_sync(0xFFFFFFFFu, vlo, 1);
            vlo += __shfl_xor_sync(0xFFFFFFFFu, vlo, 2);
            vhi += __shfl_xor_sync(0xFFFFFFFFu, vhi, 1);
            vhi += __shfl_xor_sync(0xFFFFFFFFu, vhi, 2);
            if ((lane & 3) == 0) {
                int rlo = mt0 * 16 + (lane >> 2);
                atomicAdd(&s.scores[rlo], vlo);
                int rhi = rlo + 8;
                if (rhi < NT) atomicAdd(&s.scores[rhi], vhi);
            }
        }
    }
    __syncthreads();

    // ---- mask ----
    if (tid < NT) {
        float sc = s.scores[tid];
        if (mask_g[(size_t)b * NT + tid] == 0) sc = -1.0e9f;
        s.scores[tid] = sc;
    }
    __syncthreads();

    // ---- softmax (warp 0) ----
    if (tid < 32) {
        float m = -3.4e38f;
        for (int t = tid; t < NT; t += 32) m = fmaxf(m, s.scores[t]);
        #pragma unroll
        for (int o = 16; o; o >>= 1) m = fmaxf(m, __shfl_xor_sync(0xFFFFFFFFu, m, o));
        float sum = 0.f;
        for (int t = tid; t < NT; t += 32) {
            float e = __expf(s.scores[t] - m);
            s.weights[t] = e;
            sum += e;
        }
        #pragma unroll
        for (int o = 16; o; o >>= 1) sum += __shfl_xor_sync(0xFFFFFFFFu, sum, o);
        if (tid == 0) s.invsum = 1.0f / sum;
    }
    __syncthreads();

    // ---- out[b][d] = invsum * sum_t hist[t][d] * w[t] (hist reloaded, L2-hot) ----
    {
        int d = tid & (ND - 1);
        int g = tid >> 6;
        const float* hb = hist_g + (size_t)b * NT * ND;
        float acc = 0.f;
        for (int t = g; t < NT; t += 8) acc += hb[t * ND + d] * s.weights[t];
        s.partial[g][d] = acc;
    }
    __syncthreads();
    if (tid < ND) {
        float o = 0.f;
        #pragma unroll
        for (int g = 0; g < 8; g++) o += s.partial[g][tid];
        out[(size_t)b * ND + tid] = o * s.invsum;
    }
}

extern "C" void kernel_launch(void* const* d_in, const int* in_sizes, int n_in,
                              void* d_out, int out_size)
{
    const float* cand = (const float*)d_in[0];
    const float* hist = (const float*)d_in[1];
    const int*   mask = (const int*)  d_in[2];
    const float* W1   = (const float*)d_in[3];
    const float* b1   = (const float*)d_in[4];
    const float* W2   = (const float*)d_in[5];
    const float* b2   = (const float*)d_in[6];
    const float* W3   = (const float*)d_in[7];
    const float* b3   = (const float*)d_in[8];
    float* out        = (float*)d_out;

    const int smem = (int)sizeof(Smem);
    cudaFuncSetAttribute(attention_unit_kernel,
                         cudaFuncAttributeMaxDynamicSharedMemorySize, smem);

    attention_unit_kernel<<<NB, NTHREADS, smem>>>(cand, hist, mask, W1, b1, W2, b2, W3, b3, out);
}